// round 1
// baseline (speedup 1.0000x reference)
#include <cuda_runtime.h>
#include <math.h>

// ---------------------------------------------------------------------------
// CustomAttention: B=16, T=S=E=1024, fp32.
//   q = query@Wq^T+bq ; k = key@Wk^T+bk ; v = value@Wv^T+bv
//   w[b,i,s] = (1/32) * sum_t q[b,t,i] * k[b,s,t]
//   a = softmax_s(w) ; o[b,i,e] = sum_s a[b,i,s] v[b,s,e]
//   out = o@Wo^T + bo
// All GEMMs via mma.sync tf32 (RNA-rounded inputs, fp32 accumulate).
// ---------------------------------------------------------------------------

#define BM 128
#define BN 128
#define BKK 16
#define SST 136   // smem row stride (BM + 8 pad) -> conflict-free fragment LDS

// Scratch (device globals: allocation-free rule). 4 x 64 MB.
__device__ float g_q[16u * 1024u * 1024u];
__device__ float g_k[16u * 1024u * 1024u];
__device__ float g_v[16u * 1024u * 1024u];
__device__ float g_w[16u * 1024u * 1024u];

__device__ __forceinline__ unsigned f2tf(float x) {
    unsigned u;
    asm("cvt.rna.tf32.f32 %0, %1;" : "=r"(u) : "f"(x));
    return u;
}

// Generic batched GEMM:
//   C[z][m][n] = scale * sum_k A(m,k)*B(n,k) (+ bias[n])
// AK1:  A(m,k) = A[m*sA + k]      (k unit stride)
// !AK1: A(m,k) = A[k*sA + m]      (m unit stride)
// BK1:  B(n,k) = B[n*sB + k]
// !BK1: B(n,k) = B[k*sB + n]
// M,N multiples of 128; K multiple of 16. C row-major [M,N].
template <bool AK1, bool BK1, bool BIAS>
__global__ void __launch_bounds__(256, 2)
gemm_tf32(const float* __restrict__ A, const float* __restrict__ B,
          const float* __restrict__ bias, float* __restrict__ C,
          int M, int N, int K,
          long long sA, long long sB,
          long long bsA, long long bsB, long long bsC,
          float scale) {
    const int tid  = threadIdx.x;
    const int lane = tid & 31;
    const int warp = tid >> 5;
    const int wm   = (warp & 1) << 6;  // warp M origin: 0 / 64
    const int wn   = (warp >> 1) << 5; // warp N origin: 0/32/64/96
    const long long bm = (long long)blockIdx.y * BM;
    const long long bn = (long long)blockIdx.x * BN;

    A += (long long)blockIdx.z * bsA;
    B += (long long)blockIdx.z * bsB;
    C += (long long)blockIdx.z * bsC;

    __shared__ unsigned As[2][BKK * SST];
    __shared__ unsigned Bs[2][BKK * SST];

    float acc[4][4][4];
#pragma unroll
    for (int i = 0; i < 4; i++)
#pragma unroll
        for (int j = 0; j < 4; j++)
#pragma unroll
            for (int l = 0; l < 4; l++) acc[i][j][l] = 0.f;

    float rA[8], rB[8];
    const int NT = K / BKK;

    // ---- prologue: global load tile 0 -> regs -> smem buf 0 ----
    if (AK1) {
#pragma unroll
        for (int i = 0; i < 8; i++) {
            int e = tid + (i << 8); int m = e >> 4; int k = e & 15;
            rA[i] = A[(bm + m) * sA + k];
        }
    } else {
#pragma unroll
        for (int i = 0; i < 8; i++) {
            int e = tid + (i << 8); int k = e >> 7; int m = e & 127;
            rA[i] = A[(long long)k * sA + bm + m];
        }
    }
    if (BK1) {
#pragma unroll
        for (int i = 0; i < 8; i++) {
            int e = tid + (i << 8); int m = e >> 4; int k = e & 15;
            rB[i] = B[(bn + m) * sB + k];
        }
    } else {
#pragma unroll
        for (int i = 0; i < 8; i++) {
            int e = tid + (i << 8); int k = e >> 7; int m = e & 127;
            rB[i] = B[(long long)k * sB + bn + m];
        }
    }
    if (AK1) {
#pragma unroll
        for (int i = 0; i < 8; i++) {
            int e = tid + (i << 8); int m = e >> 4; int k = e & 15;
            As[0][k * SST + m] = f2tf(rA[i]);
        }
    } else {
#pragma unroll
        for (int i = 0; i < 8; i++) {
            int e = tid + (i << 8); int k = e >> 7; int m = e & 127;
            As[0][k * SST + m] = f2tf(rA[i]);
        }
    }
    if (BK1) {
#pragma unroll
        for (int i = 0; i < 8; i++) {
            int e = tid + (i << 8); int m = e >> 4; int k = e & 15;
            Bs[0][k * SST + m] = f2tf(rB[i]);
        }
    } else {
#pragma unroll
        for (int i = 0; i < 8; i++) {
            int e = tid + (i << 8); int k = e >> 7; int m = e & 127;
            Bs[0][k * SST + m] = f2tf(rB[i]);
        }
    }
    __syncthreads();

    // ---- main loop: double-buffered ----
    for (int kt = 0; kt < NT; kt++) {
        const int buf = kt & 1;
        const bool more = (kt + 1) < NT;

        if (more) {
            const long long k0 = (long long)(kt + 1) * BKK;
            if (AK1) {
#pragma unroll
                for (int i = 0; i < 8; i++) {
                    int e = tid + (i << 8); int m = e >> 4; int k = e & 15;
                    rA[i] = A[(bm + m) * sA + k0 + k];
                }
            } else {
#pragma unroll
                for (int i = 0; i < 8; i++) {
                    int e = tid + (i << 8); int k = e >> 7; int m = e & 127;
                    rA[i] = A[(k0 + k) * sA + bm + m];
                }
            }
            if (BK1) {
#pragma unroll
                for (int i = 0; i < 8; i++) {
                    int e = tid + (i << 8); int m = e >> 4; int k = e & 15;
                    rB[i] = B[(bn + m) * sB + k0 + k];
                }
            } else {
#pragma unroll
                for (int i = 0; i < 8; i++) {
                    int e = tid + (i << 8); int k = e >> 7; int m = e & 127;
                    rB[i] = B[(k0 + k) * sB + bn + m];
                }
            }
        }

        // compute on smem[buf]: two k8 steps
#pragma unroll
        for (int k8 = 0; k8 < BKK; k8 += 8) {
            unsigned a[4][4], bb[4][2];
            const int kr = lane & 3;
            const int gr = lane >> 2;
#pragma unroll
            for (int mt = 0; mt < 4; mt++) {
                const unsigned* p = &As[buf][(k8 + kr) * SST + wm + (mt << 4) + gr];
                a[mt][0] = p[0];
                a[mt][1] = p[8];
                a[mt][2] = p[4 * SST];
                a[mt][3] = p[4 * SST + 8];
            }
#pragma unroll
            for (int nt = 0; nt < 4; nt++) {
                const unsigned* p = &Bs[buf][(k8 + kr) * SST + wn + (nt << 3) + gr];
                bb[nt][0] = p[0];
                bb[nt][1] = p[4 * SST];
            }
#pragma unroll
            for (int mt = 0; mt < 4; mt++)
#pragma unroll
                for (int nt = 0; nt < 4; nt++)
                    asm volatile(
                        "mma.sync.aligned.m16n8k8.row.col.f32.tf32.tf32.f32 "
                        "{%0,%1,%2,%3}, {%4,%5,%6,%7}, {%8,%9}, {%0,%1,%2,%3};"
                        : "+f"(acc[mt][nt][0]), "+f"(acc[mt][nt][1]),
                          "+f"(acc[mt][nt][2]), "+f"(acc[mt][nt][3])
                        : "r"(a[mt][0]), "r"(a[mt][1]), "r"(a[mt][2]), "r"(a[mt][3]),
                          "r"(bb[nt][0]), "r"(bb[nt][1]));
        }

        if (more) {
            const int nb = buf ^ 1;
            if (AK1) {
#pragma unroll
                for (int i = 0; i < 8; i++) {
                    int e = tid + (i << 8); int m = e >> 4; int k = e & 15;
                    As[nb][k * SST + m] = f2tf(rA[i]);
                }
            } else {
#pragma unroll
                for (int i = 0; i < 8; i++) {
                    int e = tid + (i << 8); int k = e >> 7; int m = e & 127;
                    As[nb][k * SST + m] = f2tf(rA[i]);
                }
            }
            if (BK1) {
#pragma unroll
                for (int i = 0; i < 8; i++) {
                    int e = tid + (i << 8); int m = e >> 4; int k = e & 15;
                    Bs[nb][k * SST + m] = f2tf(rB[i]);
                }
            } else {
#pragma unroll
                for (int i = 0; i < 8; i++) {
                    int e = tid + (i << 8); int k = e >> 7; int m = e & 127;
                    Bs[nb][k * SST + m] = f2tf(rB[i]);
                }
            }
        }
        __syncthreads();
    }

    // ---- epilogue ----
#pragma unroll
    for (int mt = 0; mt < 4; mt++) {
#pragma unroll
        for (int nt = 0; nt < 4; nt++) {
            const long long row = bm + wm + (mt << 4) + (lane >> 2);
            const int col = (int)bn + wn + (nt << 3) + ((lane & 3) << 1);
            float b0 = 0.f, b1 = 0.f;
            if (BIAS) { b0 = bias[col]; b1 = bias[col + 1]; }
            float2 v0 = make_float2(acc[mt][nt][0] * scale + b0,
                                    acc[mt][nt][1] * scale + b1);
            float2 v1 = make_float2(acc[mt][nt][2] * scale + b0,
                                    acc[mt][nt][3] * scale + b1);
            *(float2*)&C[row * (long long)N + col] = v0;
            *(float2*)&C[(row + 8) * (long long)N + col] = v1;
        }
    }
}

// ---------------------------------------------------------------------------
// Row softmax over 1024 contiguous elements, in place. 1 block per row.
// ---------------------------------------------------------------------------
__device__ __forceinline__ float warpMax(float v) {
#pragma unroll
    for (int o = 16; o; o >>= 1) v = fmaxf(v, __shfl_xor_sync(0xffffffffu, v, o));
    return v;
}
__device__ __forceinline__ float warpSum(float v) {
#pragma unroll
    for (int o = 16; o; o >>= 1) v += __shfl_xor_sync(0xffffffffu, v, o);
    return v;
}

__global__ void softmax1024(float* __restrict__ W) {
    const long long row = blockIdx.x;
    float4* p = (float4*)(W + row * 1024);
    const int tid = threadIdx.x;  // 256 threads
    float4 x = p[tid];

    float m = fmaxf(fmaxf(x.x, x.y), fmaxf(x.z, x.w));
    m = warpMax(m);
    __shared__ float sm[8];
    __shared__ float ss[8];
    if ((tid & 31) == 0) sm[tid >> 5] = m;
    __syncthreads();
    if (tid < 32) {
        float v = (tid < 8) ? sm[tid] : -1e30f;
        v = warpMax(v);
        if (tid == 0) sm[0] = v;
    }
    __syncthreads();
    m = sm[0];

    float e0 = __expf(x.x - m), e1 = __expf(x.y - m),
          e2 = __expf(x.z - m), e3 = __expf(x.w - m);
    float s = e0 + e1 + e2 + e3;
    s = warpSum(s);
    if ((tid & 31) == 0) ss[tid >> 5] = s;
    __syncthreads();
    if (tid < 32) {
        float v = (tid < 8) ? ss[tid] : 0.f;
        v = warpSum(v);
        if (tid == 0) ss[0] = v;
    }
    __syncthreads();
    const float inv = 1.0f / ss[0];
    p[tid] = make_float4(e0 * inv, e1 * inv, e2 * inv, e3 * inv);
}

// ---------------------------------------------------------------------------
extern "C" void kernel_launch(void* const* d_in, const int* in_sizes, int n_in,
                              void* d_out, int out_size) {
    const float* query = (const float*)d_in[0];
    const float* key   = (const float*)d_in[1];
    const float* value = (const float*)d_in[2];
    const float* Wq    = (const float*)d_in[3];
    const float* bq    = (const float*)d_in[4];
    const float* Wk    = (const float*)d_in[5];
    const float* bk    = (const float*)d_in[6];
    const float* Wv    = (const float*)d_in[7];
    const float* bv    = (const float*)d_in[8];
    const float* Wo    = (const float*)d_in[9];
    const float* bo    = (const float*)d_in[10];
    float* out = (float*)d_out;

    float *q, *k, *v, *w;
    cudaGetSymbolAddress((void**)&q, g_q);
    cudaGetSymbolAddress((void**)&k, g_k);
    cudaGetSymbolAddress((void**)&v, g_v);
    cudaGetSymbolAddress((void**)&w, g_w);

    const long long MB = 1024LL * 1024LL;  // per-batch matrix elements
    dim3 blk(256);
    dim3 gp(1024 / BN, 16384 / BM, 1);  // projections: M=16384
    dim3 ga(1024 / BN, 1024 / BM, 16);  // per-batch attention GEMMs

    // q/k/v projections: C = X @ W^T + b   (A k-unit, B k-unit)
    gemm_tf32<true, true, true><<<gp, blk>>>(query, Wq, bq, q, 16384, 1024, 1024,
                                             1024, 1024, 0, 0, 0, 1.0f);
    gemm_tf32<true, true, true><<<gp, blk>>>(key, Wk, bk, k, 16384, 1024, 1024,
                                             1024, 1024, 0, 0, 0, 1.0f);
    gemm_tf32<true, true, true><<<gp, blk>>>(value, Wv, bv, v, 16384, 1024, 1024,
                                             1024, 1024, 0, 0, 0, 1.0f);

    // logits: w[b,i,s] = (1/32) sum_t q[b,t,i] * k[b,s,t]
    //   A(m=i,k=t) = q[t*1024+i]  -> m-unit (!AK1, sA = 1024)
    //   B(n=s,k=t) = k[s*1024+t]  -> k-unit (BK1,  sB = 1024)
    gemm_tf32<false, true, false><<<ga, blk>>>(q, k, nullptr, w, 1024, 1024, 1024,
                                               1024, 1024, MB, MB, MB, 0.03125f);

    // softmax over last dim (rows of w)
    softmax1024<<<16 * 1024, 256>>>(w);

    // o[b,i,e] = sum_s a[b,i,s] * v[b,s,e]   (o reuses g_q)
    //   A(m=i,k=s) = w[i*1024+s] -> k-unit (AK1, sA=1024)
    //   B(n=e,k=s) = v[s*1024+e] -> n-unit (!BK1, sB=1024)
    gemm_tf32<true, false, false><<<ga, blk>>>(w, v, nullptr, q, 1024, 1024, 1024,
                                               1024, 1024, MB, MB, MB, 1.0f);

    // out = o @ Wo^T + bo
    gemm_tf32<true, true, true><<<gp, blk>>>(q, Wo, bo, out, 16384, 1024, 1024,
                                             1024, 1024, 0, 0, 0, 1.0f);
}

// round 3
// speedup vs baseline: 1.0618x; 1.0618x over previous
#include <cuda_runtime.h>
#include <cstdint>
#include <math.h>

// ============================================================================
// CustomAttention B=16, T=S=E=1024 fp32. Legacy mma.sync tf32 path
// (tcgen05 is unavailable: harness emits compute_103 PTX, no 'a' features).
// Block tile 128(M) x 256(N) x 16(K), 8 warps of 64x64, double-buffered smem,
// float4 global loads, pre-rounded tf32 inputs (no cvt in mainloop).
// ============================================================================

#define LDA 136               // A smem row stride (floats): 136%32==8 -> conflict-free frags
#define LDB 264               // B smem row stride
#define ASTG (16 * LDA)
#define BSTG (16 * LDB)
#define SMEM_FLOATS (2 * ASTG + 2 * BSTG)   // 12800 floats = 51200 B

// ---------------- scratch (device globals; no allocation allowed) -----------
__device__ float g_rq[16u * 1024u * 1024u];
__device__ float g_rk[16u * 1024u * 1024u];
__device__ float g_rv[16u * 1024u * 1024u];
__device__ float g_rw[4u * 1024u * 1024u];   // Wq|Wk|Wv|Wo rounded
__device__ float g_q [16u * 1024u * 1024u];
__device__ float g_k [16u * 1024u * 1024u];
__device__ float g_v [16u * 1024u * 1024u];
__device__ float g_w [16u * 1024u * 1024u];
__device__ float g_o [16u * 1024u * 1024u];

__device__ __forceinline__ float f2tf(float x) {
    unsigned u;
    asm("cvt.rna.tf32.f32 %0, %1;" : "=r"(u) : "f"(x));
    return __uint_as_float(u);
}

__device__ __forceinline__ void mma8(float* d, const float* a, const float* b) {
    asm volatile(
        "mma.sync.aligned.m16n8k8.row.col.f32.tf32.tf32.f32 "
        "{%0,%1,%2,%3}, {%4,%5,%6,%7}, {%8,%9}, {%0,%1,%2,%3};"
        : "+f"(d[0]), "+f"(d[1]), "+f"(d[2]), "+f"(d[3])
        : "r"(__float_as_uint(a[0])), "r"(__float_as_uint(a[1])),
          "r"(__float_as_uint(a[2])), "r"(__float_as_uint(a[3])),
          "r"(__float_as_uint(b[0])), "r"(__float_as_uint(b[1])));
}

// ============================================================================
// Batched GEMM: C[z][m][n] = scale * sum_k A(m,k)*B(n,k) (+ bias[n])
//   AK1:  A(m,k) = A[m*sA + k]   (k unit stride)   else A(m,k) = A[k*sA + m]
//   BK1:  B(n,k) = B[n*sB + k]                     else B(n,k) = B[k*sB + n]
// M mult of 128 (grid.y), N mult of 256 (grid.x), K = 1024. C row-major ldC.
// ============================================================================
template <bool AK1, bool BK1, bool BIAS, bool ROUND>
__global__ void __launch_bounds__(256, 1)
gemm_v2(const float* __restrict__ A, const float* __restrict__ B,
        const float* __restrict__ bias, float* __restrict__ C,
        long long bsA, long long bsB, long long bsC,
        int sA, int sB, int ldC, float scale) {
    extern __shared__ float sm[];
    float* As = sm;                // [2][16][LDA]
    float* Bs = sm + 2 * ASTG;     // [2][16][LDB]

    const int tid  = threadIdx.x;
    const int lane = tid & 31;
    const int warp = tid >> 5;
    const int wm = (warp & 1) << 6;   // 0 / 64
    const int wn = (warp >> 1) << 6;  // 0 / 64 / 128 / 192
    const int gr = lane >> 2;
    const int kr = lane & 3;
    const int bn = blockIdx.x << 8;
    const int bm = blockIdx.y << 7;

    A += (long long)blockIdx.z * bsA;
    B += (long long)blockIdx.z * bsB;
    C += (long long)blockIdx.z * bsC;

    // ---- global pointers & smem store bases (computed once) ----
    const float* pA;
    long long dA;   // i=1 offset
    long long stepA;
    int aSts;       // smem float index base (stage 0)
    if (AK1) {
        const int m_a = tid >> 2, kq = tid & 3;
        pA = A + (long long)(bm + m_a) * sA + 4 * kq;
        dA = 64LL * sA;
        stepA = 16;
        aSts = 4 * kq * LDA + m_a;
    } else {
        const int k_a = tid >> 5, m4 = (tid & 31) << 2;
        pA = A + (long long)k_a * sA + bm + m4;
        dA = 8LL * sA;
        stepA = 16LL * sA;
        aSts = k_a * LDA + m4;
    }
    const float* pB;
    long long dB, stepB;
    int bSts;
    if (BK1) {
        const int n_b = tid >> 2, kq = tid & 3;
        pB = B + (long long)(bn + n_b) * sB + 4 * kq;
        dB = 64LL * sB;
        stepB = 16;
        bSts = 4 * kq * LDB + n_b;
    } else {
        const int k_b = tid >> 6, n4 = (tid & 63) << 2;
        pB = B + (long long)k_b * sB + bn + n4;
        dB = 4LL * sB;
        stepB = 16LL * sB;
        bSts = k_b * LDB + n4;
    }
    const int aFrag = kr * LDA + wm + gr;
    const int bFrag = kr * LDB + wn + gr;

    float acc[4][8][4];
#pragma unroll
    for (int i = 0; i < 4; i++)
#pragma unroll
        for (int j = 0; j < 8; j++)
#pragma unroll
            for (int l = 0; l < 4; l++) acc[i][j][l] = 0.f;

    float4 rA[2], rB[4];

    // ---- prologue: tile 0 -> smem buf 0 ----
#pragma unroll
    for (int i = 0; i < 2; i++) rA[i] = *(const float4*)(pA + i * dA);
#pragma unroll
    for (int i = 0; i < 4; i++) rB[i] = *(const float4*)(pB + i * dB);
    pA += stepA; pB += stepB;
    if (AK1) {
#pragma unroll
        for (int i = 0; i < 2; i++) {
            const int o = aSts + i * 64;
            As[o] = rA[i].x; As[o + LDA] = rA[i].y;
            As[o + 2 * LDA] = rA[i].z; As[o + 3 * LDA] = rA[i].w;
        }
    } else {
#pragma unroll
        for (int i = 0; i < 2; i++)
            *(float4*)&As[aSts + i * 8 * LDA] = rA[i];
    }
    if (BK1) {
#pragma unroll
        for (int i = 0; i < 4; i++) {
            const int o = bSts + i * 64;
            Bs[o] = rB[i].x; Bs[o + LDB] = rB[i].y;
            Bs[o + 2 * LDB] = rB[i].z; Bs[o + 3 * LDB] = rB[i].w;
        }
    } else {
#pragma unroll
        for (int i = 0; i < 4; i++)
            *(float4*)&Bs[bSts + i * 4 * LDB] = rB[i];
    }
    __syncthreads();

    // ---- main loop over 64 k-tiles ----
    for (int kt = 0; kt < 64; kt++) {
        const int buf = kt & 1;
        const bool more = kt < 63;
        if (more) {
#pragma unroll
            for (int i = 0; i < 2; i++) rA[i] = *(const float4*)(pA + i * dA);
#pragma unroll
            for (int i = 0; i < 4; i++) rB[i] = *(const float4*)(pB + i * dB);
            pA += stepA; pB += stepB;
        }

        {
            const float* pa = As + buf * ASTG + aFrag;
            const float* pb = Bs + buf * BSTG + bFrag;
#pragma unroll
            for (int k8 = 0; k8 < 2; k8++) {
                float a[4][4], b[8][2];
#pragma unroll
                for (int mt = 0; mt < 4; mt++) {
                    const float* p = pa + k8 * (8 * LDA) + mt * 16;
                    a[mt][0] = p[0];
                    a[mt][1] = p[8];
                    a[mt][2] = p[4 * LDA];
                    a[mt][3] = p[4 * LDA + 8];
                }
#pragma unroll
                for (int nt = 0; nt < 8; nt++) {
                    const float* p = pb + k8 * (8 * LDB) + nt * 8;
                    b[nt][0] = p[0];
                    b[nt][1] = p[4 * LDB];
                }
#pragma unroll
                for (int mt = 0; mt < 4; mt++)
#pragma unroll
                    for (int nt = 0; nt < 8; nt++)
                        mma8(acc[mt][nt], a[mt], b[nt]);
            }
        }

        if (more) {
            const int nb = (buf ^ 1);
            if (AK1) {
#pragma unroll
                for (int i = 0; i < 2; i++) {
                    const int o = nb * ASTG + aSts + i * 64;
                    As[o] = rA[i].x; As[o + LDA] = rA[i].y;
                    As[o + 2 * LDA] = rA[i].z; As[o + 3 * LDA] = rA[i].w;
                }
            } else {
#pragma unroll
                for (int i = 0; i < 2; i++)
                    *(float4*)&As[nb * ASTG + aSts + i * 8 * LDA] = rA[i];
            }
            if (BK1) {
#pragma unroll
                for (int i = 0; i < 4; i++) {
                    const int o = nb * BSTG + bSts + i * 64;
                    Bs[o] = rB[i].x; Bs[o + LDB] = rB[i].y;
                    Bs[o + 2 * LDB] = rB[i].z; Bs[o + 3 * LDB] = rB[i].w;
                }
            } else {
#pragma unroll
                for (int i = 0; i < 4; i++)
                    *(float4*)&Bs[nb * BSTG + bSts + i * 4 * LDB] = rB[i];
            }
        }
        __syncthreads();
    }

    // ---- epilogue ----
#pragma unroll
    for (int mt = 0; mt < 4; mt++) {
        const long long r0 = (long long)(bm + wm + mt * 16 + gr) * ldC;
#pragma unroll
        for (int nt = 0; nt < 8; nt++) {
            const int col = bn + wn + nt * 8 + kr * 2;
            float b0 = 0.f, b1 = 0.f;
            if (BIAS) {
                float2 bb = *(const float2*)(bias + col);
                b0 = bb.x; b1 = bb.y;
            }
            float x0 = acc[mt][nt][0] * scale + b0;
            float x1 = acc[mt][nt][1] * scale + b1;
            float x2 = acc[mt][nt][2] * scale + b0;
            float x3 = acc[mt][nt][3] * scale + b1;
            if (ROUND) {
                x0 = f2tf(x0); x1 = f2tf(x1); x2 = f2tf(x2); x3 = f2tf(x3);
            }
            *(float2*)&C[r0 + col] = make_float2(x0, x1);
            *(float2*)&C[r0 + 8LL * ldC + col] = make_float2(x2, x3);
        }
    }
}

// ---------------- pre-round (RNA -> tf32) ------------------------------------
__global__ void round_pass(const float* __restrict__ in, float* __restrict__ out,
                           int n) {
    int i = (blockIdx.x * blockDim.x + threadIdx.x) * 4;
    if (i < n) {
        float4 v = *(const float4*)(in + i);
        v.x = f2tf(v.x); v.y = f2tf(v.y); v.z = f2tf(v.z); v.w = f2tf(v.w);
        *(float4*)(out + i) = v;
    }
}

// ---------------- softmax over rows of 1024, in place, rounds output ---------
__device__ __forceinline__ float warpMax(float v) {
#pragma unroll
    for (int o = 16; o; o >>= 1) v = fmaxf(v, __shfl_xor_sync(0xffffffffu, v, o));
    return v;
}
__device__ __forceinline__ float warpSum(float v) {
#pragma unroll
    for (int o = 16; o; o >>= 1) v += __shfl_xor_sync(0xffffffffu, v, o);
    return v;
}
__global__ void softmax1024(float* __restrict__ W) {
    const long long row = blockIdx.x;
    float4* p = (float4*)(W + row * 1024);
    const int tid = threadIdx.x;  // 256
    float4 x = p[tid];
    float m = fmaxf(fmaxf(x.x, x.y), fmaxf(x.z, x.w));
    m = warpMax(m);
    __shared__ float sm[8], ss[8];
    if ((tid & 31) == 0) sm[tid >> 5] = m;
    __syncthreads();
    if (tid < 32) {
        float v = (tid < 8) ? sm[tid] : -1e30f;
        v = warpMax(v);
        if (tid == 0) sm[0] = v;
    }
    __syncthreads();
    m = sm[0];
    float e0 = __expf(x.x - m), e1 = __expf(x.y - m),
          e2 = __expf(x.z - m), e3 = __expf(x.w - m);
    float s = e0 + e1 + e2 + e3;
    s = warpSum(s);
    if ((tid & 31) == 0) ss[tid >> 5] = s;
    __syncthreads();
    if (tid < 32) {
        float v = (tid < 8) ? ss[tid] : 0.f;
        v = warpSum(v);
        if (tid == 0) ss[0] = v;
    }
    __syncthreads();
    const float inv = 1.0f / ss[0];
    p[tid] = make_float4(f2tf(e0 * inv), f2tf(e1 * inv),
                         f2tf(e2 * inv), f2tf(e3 * inv));
}

// ---------------- host side ---------------------------------------------------
extern "C" void kernel_launch(void* const* d_in, const int* in_sizes, int n_in,
                              void* d_out, int out_size) {
    const float* query = (const float*)d_in[0];
    const float* key   = (const float*)d_in[1];
    const float* value = (const float*)d_in[2];
    const float* Wq = (const float*)d_in[3];
    const float* bq = (const float*)d_in[4];
    const float* Wk = (const float*)d_in[5];
    const float* bk = (const float*)d_in[6];
    const float* Wv = (const float*)d_in[7];
    const float* bv = (const float*)d_in[8];
    const float* Wo = (const float*)d_in[9];
    const float* bo = (const float*)d_in[10];
    float* out = (float*)d_out;

    float *rq, *rk, *rv, *rw, *q, *k, *v, *w, *o;
    cudaGetSymbolAddress((void**)&rq, g_rq);
    cudaGetSymbolAddress((void**)&rk, g_rk);
    cudaGetSymbolAddress((void**)&rv, g_rv);
    cudaGetSymbolAddress((void**)&rw, g_rw);
    cudaGetSymbolAddress((void**)&q, g_q);
    cudaGetSymbolAddress((void**)&k, g_k);
    cudaGetSymbolAddress((void**)&v, g_v);
    cudaGetSymbolAddress((void**)&w, g_w);
    cudaGetSymbolAddress((void**)&o, g_o);

    const int SMEM = SMEM_FLOATS * 4;
    cudaFuncSetAttribute(gemm_v2<true, true, true, true>,
                         cudaFuncAttributeMaxDynamicSharedMemorySize, SMEM);
    cudaFuncSetAttribute(gemm_v2<false, true, false, false>,
                         cudaFuncAttributeMaxDynamicSharedMemorySize, SMEM);
    cudaFuncSetAttribute(gemm_v2<true, false, false, true>,
                         cudaFuncAttributeMaxDynamicSharedMemorySize, SMEM);
    cudaFuncSetAttribute(gemm_v2<true, true, true, false>,
                         cudaFuncAttributeMaxDynamicSharedMemorySize, SMEM);

    const int BIG = 16 * 1024 * 1024, WSZ = 1024 * 1024;
    round_pass<<<BIG / 1024, 256>>>(query, rq, BIG);
    round_pass<<<BIG / 1024, 256>>>(key, rk, BIG);
    round_pass<<<BIG / 1024, 256>>>(value, rv, BIG);
    round_pass<<<WSZ / 1024, 256>>>(Wq, rw + 0 * WSZ, WSZ);
    round_pass<<<WSZ / 1024, 256>>>(Wk, rw + 1 * WSZ, WSZ);
    round_pass<<<WSZ / 1024, 256>>>(Wv, rw + 2 * WSZ, WSZ);
    round_pass<<<WSZ / 1024, 256>>>(Wo, rw + 3 * WSZ, WSZ);

    const long long MB = 1024LL * 1024LL;
    dim3 blk(256);
    dim3 gp(4, 128, 1);   // projections: M=16384, N=1024
    dim3 ga(4, 8, 16);    // attention:   M=1024,  N=1024, batch 16

    // q/k/v = X @ W^T + b (k-unit both), rounded outputs
    gemm_v2<true, true, true, true><<<gp, blk, SMEM>>>(
        rq, rw + 0 * WSZ, bq, q, 0, 0, 0, 1024, 1024, 1024, 1.0f);
    gemm_v2<true, true, true, true><<<gp, blk, SMEM>>>(
        rk, rw + 1 * WSZ, bk, k, 0, 0, 0, 1024, 1024, 1024, 1.0f);
    gemm_v2<true, true, true, true><<<gp, blk, SMEM>>>(
        rv, rw + 2 * WSZ, bv, v, 0, 0, 0, 1024, 1024, 1024, 1.0f);

    // w[b,i,s] = (1/32) sum_t q[b,t,i]*k[b,s,t]: A=q m-unit, B=k k-unit
    gemm_v2<false, true, false, false><<<ga, blk, SMEM>>>(
        q, k, nullptr, w, MB, MB, MB, 1024, 1024, 1024, 0.03125f);

    softmax1024<<<16 * 1024, 256>>>(w);

    // o[b,i,e] = sum_s a[b,i,s]*v[b,s,e]: A=w k-unit, B=v n-unit
    gemm_v2<true, false, false, true><<<ga, blk, SMEM>>>(
        w, v, nullptr, o, MB, MB, MB, 1024, 1024, 1024, 1.0f);

    // out = o @ Wo^T + bo
    gemm_v2<true, true, true, false><<<gp, blk, SMEM>>>(
        o, rw + 3 * WSZ, bo, out, 0, 0, 0, 1024, 1024, 1024, 1.0f);
}

// round 4
// speedup vs baseline: 1.4268x; 1.3437x over previous
#include <cuda_runtime.h>
#include <cstdint>
#include <math.h>

// ============================================================================
// CustomAttention B=16, T=S=E=1024 fp32. mma.sync tf32 + cp.async 4-stage.
// (tcgen05 unavailable: harness emits compute_103 PTX -> no 'a' features.)
// Block tile 128x128x16, 8 warps of 64x32, 2 CTAs/SM, pre-rounded tf32 inputs.
// ============================================================================

#define LD1 20      // [m][k] smem row stride (floats): conflict-free, 16B-aligned rows
#define LD2 136     // [k][m] smem row stride
#define A_OFF 0
#define B_OFF 2560              // floats
#define STG_FLOATS 5120
#define STG_BYTES 20480
#define NSTAGE 4
#define SMEM_BYTES (NSTAGE * STG_BYTES)   // 81920

// ---------------- scratch (device globals; no allocation allowed) -----------
__device__ float g_rq[16u * 1024u * 1024u];
__device__ float g_rk[16u * 1024u * 1024u];
__device__ float g_rv[16u * 1024u * 1024u];
__device__ float g_rw[4u * 1024u * 1024u];   // Wq|Wk|Wv|Wo rounded
__device__ float g_q [16u * 1024u * 1024u];
__device__ float g_k [16u * 1024u * 1024u];
__device__ float g_v [16u * 1024u * 1024u];
__device__ float g_w [16u * 1024u * 1024u];
__device__ float g_o [16u * 1024u * 1024u];

__device__ __forceinline__ float f2tf(float x) {
    unsigned u;
    asm("cvt.rna.tf32.f32 %0, %1;" : "=r"(u) : "f"(x));
    return __uint_as_float(u);
}
__device__ __forceinline__ void cpa16(uint32_t s, const float* g) {
    asm volatile("cp.async.cg.shared.global [%0], [%1], 16;"
                 :: "r"(s), "l"(g));
}
#define CP_COMMIT() asm volatile("cp.async.commit_group;")
#define CP_WAIT2()  asm volatile("cp.async.wait_group 2;")

__device__ __forceinline__ void mma8(float* d, const float* a, const float* b) {
    asm volatile(
        "mma.sync.aligned.m16n8k8.row.col.f32.tf32.tf32.f32 "
        "{%0,%1,%2,%3}, {%4,%5,%6,%7}, {%8,%9}, {%0,%1,%2,%3};"
        : "+f"(d[0]), "+f"(d[1]), "+f"(d[2]), "+f"(d[3])
        : "r"(__float_as_uint(a[0])), "r"(__float_as_uint(a[1])),
          "r"(__float_as_uint(a[2])), "r"(__float_as_uint(a[3])),
          "r"(__float_as_uint(b[0])), "r"(__float_as_uint(b[1])));
}

// ============================================================================
// Batched GEMM: C[z][m][n] = scale * sum_k A(m,k)*B(n,k) (+ bias[n])
//   AK1:  A(m,k) = A[m*sA + k]   else A(m,k) = A[k*sA + m]   (same for B)
// M,N multiples of 128, K = 1024. C row-major ldC.
// ============================================================================
template <bool AK1, bool BK1, bool BIAS, bool ROUND>
__global__ void __launch_bounds__(256, 2)
gemm_v3(const float* __restrict__ A, const float* __restrict__ B,
        const float* __restrict__ bias, float* __restrict__ C,
        long long bsA, long long bsB, long long bsC,
        int sA, int sB, int ldC, float scale) {
    extern __shared__ float sm[];
    const uint32_t smb = (uint32_t)__cvta_generic_to_shared(sm);

    const int tid  = threadIdx.x;
    const int lane = tid & 31;
    const int warp = tid >> 5;
    const int wm = (warp & 1) << 6;   // 0 / 64
    const int wn = (warp >> 1) << 5;  // 0 / 32 / 64 / 96
    const int gr = lane >> 2;
    const int kr = lane & 3;
    const int bn = blockIdx.x << 7;
    const int bm = blockIdx.y << 7;

    A += (long long)blockIdx.z * bsA;
    B += (long long)blockIdx.z * bsB;
    C += (long long)blockIdx.z * bsC;

    // ---- cp.async source pointers + smem byte offsets (2 chunks each) ----
    const float* gA[2];
    const float* gB[2];
    uint32_t dA[2], dB[2];
    long long stepA, stepB;
    if (AK1) {
#pragma unroll
        for (int i = 0; i < 2; i++) {
            const int c = tid + (i << 8);
            const int m = c >> 2, kq = c & 3;
            gA[i] = A + (long long)(bm + m) * sA + 4 * kq;
            dA[i] = (uint32_t)(m * LD1 + 4 * kq) * 4u;
        }
        stepA = 16;
    } else {
#pragma unroll
        for (int i = 0; i < 2; i++) {
            const int c = tid + (i << 8);
            const int k = c >> 5, m4 = (c & 31) << 2;
            gA[i] = A + (long long)k * sA + bm + m4;
            dA[i] = (uint32_t)(k * LD2 + m4) * 4u;
        }
        stepA = 16LL * sA;
    }
    if (BK1) {
#pragma unroll
        for (int i = 0; i < 2; i++) {
            const int c = tid + (i << 8);
            const int n = c >> 2, kq = c & 3;
            gB[i] = B + (long long)(bn + n) * sB + 4 * kq;
            dB[i] = (uint32_t)(B_OFF + n * LD1 + 4 * kq) * 4u;
        }
        stepB = 16;
    } else {
#pragma unroll
        for (int i = 0; i < 2; i++) {
            const int c = tid + (i << 8);
            const int k = c >> 5, n4 = (c & 31) << 2;
            gB[i] = B + (long long)k * sB + bn + n4;
            dB[i] = (uint32_t)(B_OFF + k * LD2 + n4) * 4u;
        }
        stepB = 16LL * sB;
    }

    float acc[4][4][4];
#pragma unroll
    for (int i = 0; i < 4; i++)
#pragma unroll
        for (int j = 0; j < 4; j++)
#pragma unroll
            for (int l = 0; l < 4; l++) acc[i][j][l] = 0.f;

    // ---- prologue: stages 0..2 ----
#pragma unroll
    for (int s = 0; s < 3; s++) {
        const uint32_t sb = smb + s * STG_BYTES;
        cpa16(sb + dA[0], gA[0]); cpa16(sb + dA[1], gA[1]);
        cpa16(sb + dB[0], gB[0]); cpa16(sb + dB[1], gB[1]);
        gA[0] += stepA; gA[1] += stepA;
        gB[0] += stepB; gB[1] += stepB;
        CP_COMMIT();
    }

    // ---- main loop over 64 k-tiles ----
    for (int kt = 0; kt < 64; kt++) {
        CP_WAIT2();
        __syncthreads();

        if (kt + 3 < 64) {
            const uint32_t sb = smb + ((kt + 3) & 3) * STG_BYTES;
            cpa16(sb + dA[0], gA[0]); cpa16(sb + dA[1], gA[1]);
            cpa16(sb + dB[0], gB[0]); cpa16(sb + dB[1], gB[1]);
            gA[0] += stepA; gA[1] += stepA;
            gB[0] += stepB; gB[1] += stepB;
        }
        CP_COMMIT();

        const float* As = sm + (kt & 3) * STG_FLOATS;
        const float* Bs = As + B_OFF;
#pragma unroll
        for (int k8 = 0; k8 < 2; k8++) {
            float a[4][4], b[4][2];
            if (AK1) {
#pragma unroll
                for (int mt = 0; mt < 4; mt++) {
                    const float* p = As + (wm + mt * 16 + gr) * LD1 + k8 * 8 + kr;
                    a[mt][0] = p[0];
                    a[mt][1] = p[8 * LD1];
                    a[mt][2] = p[4];
                    a[mt][3] = p[8 * LD1 + 4];
                }
            } else {
#pragma unroll
                for (int mt = 0; mt < 4; mt++) {
                    const float* p = As + (k8 * 8 + kr) * LD2 + wm + mt * 16 + gr;
                    a[mt][0] = p[0];
                    a[mt][1] = p[8];
                    a[mt][2] = p[4 * LD2];
                    a[mt][3] = p[4 * LD2 + 8];
                }
            }
            if (BK1) {
#pragma unroll
                for (int nt = 0; nt < 4; nt++) {
                    const float* p = Bs + (wn + nt * 8 + gr) * LD1 + k8 * 8 + kr;
                    b[nt][0] = p[0];
                    b[nt][1] = p[4];
                }
            } else {
#pragma unroll
                for (int nt = 0; nt < 4; nt++) {
                    const float* p = Bs + (k8 * 8 + kr) * LD2 + wn + nt * 8 + gr;
                    b[nt][0] = p[0];
                    b[nt][1] = p[4 * LD2];
                }
            }
#pragma unroll
            for (int mt = 0; mt < 4; mt++)
#pragma unroll
                for (int nt = 0; nt < 4; nt++)
                    mma8(acc[mt][nt], a[mt], b[nt]);
        }
    }

    // ---- epilogue ----
#pragma unroll
    for (int mt = 0; mt < 4; mt++) {
        const long long r0 = (long long)(bm + wm + mt * 16 + gr) * ldC;
#pragma unroll
        for (int nt = 0; nt < 4; nt++) {
            const int col = bn + wn + nt * 8 + kr * 2;
            float b0 = 0.f, b1 = 0.f;
            if (BIAS) {
                float2 bb = *(const float2*)(bias + col);
                b0 = bb.x; b1 = bb.y;
            }
            float x0 = acc[mt][nt][0] * scale + b0;
            float x1 = acc[mt][nt][1] * scale + b1;
            float x2 = acc[mt][nt][2] * scale + b0;
            float x3 = acc[mt][nt][3] * scale + b1;
            if (ROUND) {
                x0 = f2tf(x0); x1 = f2tf(x1); x2 = f2tf(x2); x3 = f2tf(x3);
            }
            *(float2*)&C[r0 + col] = make_float2(x0, x1);
            *(float2*)&C[r0 + 8LL * ldC + col] = make_float2(x2, x3);
        }
    }
}

// ---------------- pre-round (RNA -> tf32) ------------------------------------
__global__ void round_pass(const float* __restrict__ in, float* __restrict__ out,
                           int n) {
    int i = (blockIdx.x * blockDim.x + threadIdx.x) * 4;
    if (i < n) {
        float4 v = *(const float4*)(in + i);
        v.x = f2tf(v.x); v.y = f2tf(v.y); v.z = f2tf(v.z); v.w = f2tf(v.w);
        *(float4*)(out + i) = v;
    }
}

// ---------------- softmax over rows of 1024, in place, rounds output ---------
__device__ __forceinline__ float warpMax(float v) {
#pragma unroll
    for (int o = 16; o; o >>= 1) v = fmaxf(v, __shfl_xor_sync(0xffffffffu, v, o));
    return v;
}
__device__ __forceinline__ float warpSum(float v) {
#pragma unroll
    for (int o = 16; o; o >>= 1) v += __shfl_xor_sync(0xffffffffu, v, o);
    return v;
}
__global__ void softmax1024(float* __restrict__ W) {
    const long long row = blockIdx.x;
    float4* p = (float4*)(W + row * 1024);
    const int tid = threadIdx.x;  // 256
    float4 x = p[tid];
    float m = fmaxf(fmaxf(x.x, x.y), fmaxf(x.z, x.w));
    m = warpMax(m);
    __shared__ float sm[8], ss[8];
    if ((tid & 31) == 0) sm[tid >> 5] = m;
    __syncthreads();
    if (tid < 32) {
        float v = (tid < 8) ? sm[tid] : -1e30f;
        v = warpMax(v);
        if (tid == 0) sm[0] = v;
    }
    __syncthreads();
    m = sm[0];
    float e0 = __expf(x.x - m), e1 = __expf(x.y - m),
          e2 = __expf(x.z - m), e3 = __expf(x.w - m);
    float s = e0 + e1 + e2 + e3;
    s = warpSum(s);
    if ((tid & 31) == 0) ss[tid >> 5] = s;
    __syncthreads();
    if (tid < 32) {
        float v = (tid < 8) ? ss[tid] : 0.f;
        v = warpSum(v);
        if (tid == 0) ss[0] = v;
    }
    __syncthreads();
    const float inv = 1.0f / ss[0];
    p[tid] = make_float4(f2tf(e0 * inv), f2tf(e1 * inv),
                         f2tf(e2 * inv), f2tf(e3 * inv));
}

// ---------------- host side ---------------------------------------------------
extern "C" void kernel_launch(void* const* d_in, const int* in_sizes, int n_in,
                              void* d_out, int out_size) {
    const float* query = (const float*)d_in[0];
    const float* key   = (const float*)d_in[1];
    const float* value = (const float*)d_in[2];
    const float* Wq = (const float*)d_in[3];
    const float* bq = (const float*)d_in[4];
    const float* Wk = (const float*)d_in[5];
    const float* bk = (const float*)d_in[6];
    const float* Wv = (const float*)d_in[7];
    const float* bv = (const float*)d_in[8];
    const float* Wo = (const float*)d_in[9];
    const float* bo = (const float*)d_in[10];
    float* out = (float*)d_out;

    float *rq, *rk, *rv, *rw, *q, *k, *v, *w, *o;
    cudaGetSymbolAddress((void**)&rq, g_rq);
    cudaGetSymbolAddress((void**)&rk, g_rk);
    cudaGetSymbolAddress((void**)&rv, g_rv);
    cudaGetSymbolAddress((void**)&rw, g_rw);
    cudaGetSymbolAddress((void**)&q, g_q);
    cudaGetSymbolAddress((void**)&k, g_k);
    cudaGetSymbolAddress((void**)&v, g_v);
    cudaGetSymbolAddress((void**)&w, g_w);
    cudaGetSymbolAddress((void**)&o, g_o);

    cudaFuncSetAttribute(gemm_v3<true, true, true, true>,
                         cudaFuncAttributeMaxDynamicSharedMemorySize, SMEM_BYTES);
    cudaFuncSetAttribute(gemm_v3<false, true, false, false>,
                         cudaFuncAttributeMaxDynamicSharedMemorySize, SMEM_BYTES);
    cudaFuncSetAttribute(gemm_v3<true, false, false, true>,
                         cudaFuncAttributeMaxDynamicSharedMemorySize, SMEM_BYTES);
    cudaFuncSetAttribute(gemm_v3<true, true, true, false>,
                         cudaFuncAttributeMaxDynamicSharedMemorySize, SMEM_BYTES);

    const int BIG = 16 * 1024 * 1024, WSZ = 1024 * 1024;
    round_pass<<<BIG / 1024, 256>>>(query, rq, BIG);
    round_pass<<<BIG / 1024, 256>>>(key, rk, BIG);
    round_pass<<<BIG / 1024, 256>>>(value, rv, BIG);
    round_pass<<<WSZ / 1024, 256>>>(Wq, rw + 0 * WSZ, WSZ);
    round_pass<<<WSZ / 1024, 256>>>(Wk, rw + 1 * WSZ, WSZ);
    round_pass<<<WSZ / 1024, 256>>>(Wv, rw + 2 * WSZ, WSZ);
    round_pass<<<WSZ / 1024, 256>>>(Wo, rw + 3 * WSZ, WSZ);

    const long long MB = 1024LL * 1024LL;
    dim3 blk(256);
    dim3 gp(8, 128, 1);   // projections: N=1024, M=16384
    dim3 ga(8, 8, 16);    // attention:   N=1024, M=1024, batch 16

    // q/k/v = X @ W^T + b (k-unit both), rounded outputs
    gemm_v3<true, true, true, true><<<gp, blk, SMEM_BYTES>>>(
        rq, rw + 0 * WSZ, bq, q, 0, 0, 0, 1024, 1024, 1024, 1.0f);
    gemm_v3<true, true, true, true><<<gp, blk, SMEM_BYTES>>>(
        rk, rw + 1 * WSZ, bk, k, 0, 0, 0, 1024, 1024, 1024, 1.0f);
    gemm_v3<true, true, true, true><<<gp, blk, SMEM_BYTES>>>(
        rv, rw + 2 * WSZ, bv, v, 0, 0, 0, 1024, 1024, 1024, 1.0f);

    // w[b,i,s] = (1/32) sum_t q[b,t,i]*k[b,s,t]: A=q m-unit, B=k k-unit
    gemm_v3<false, true, false, false><<<ga, blk, SMEM_BYTES>>>(
        q, k, nullptr, w, MB, MB, MB, 1024, 1024, 1024, 0.03125f);

    softmax1024<<<16 * 1024, 256>>>(w);

    // o[b,i,e] = sum_s a[b,i,s]*v[b,s,e]: A=w k-unit, B=v n-unit
    gemm_v3<true, false, false, true><<<ga, blk, SMEM_BYTES>>>(
        w, v, nullptr, o, MB, MB, MB, 1024, 1024, 1024, 1.0f);

    // out = o @ Wo^T + bo
    gemm_v3<true, true, true, false><<<gp, blk, SMEM_BYTES>>>(
        o, rw + 3 * WSZ, bo, out, 0, 0, 0, 1024, 1024, 1024, 1.0f);
}

// round 5
// speedup vs baseline: 1.5081x; 1.0570x over previous
#include <cuda_runtime.h>
#include <cstdint>
#include <math.h>

// ============================================================================
// CustomAttention B=16, T=S=E=1024 fp32. mma.sync tf32 + cp.async 4-stage.
// (tcgen05 unavailable: harness emits compute_103 PTX -> no 'a' features.)
// 128-thread CTA, block 128x128x16, 4 warps of 64x64, 2 CTAs/SM.
// Pre-rounded tf32 inputs; 1.0 LDS per MMA (tensor-bound by construction).
// ============================================================================

#define LD1 20      // [m][k] smem row stride (floats)
#define LD2 136     // [k][m] smem row stride
#define B_OFF 2560              // floats (128*20)
#define STG_FLOATS 5120
#define STG_BYTES 20480
#define NSTAGE 4
#define SMEM_BYTES (NSTAGE * STG_BYTES)   // 81920

// ---------------- scratch (device globals; no allocation allowed) -----------
__device__ float g_rq[16u * 1024u * 1024u];
__device__ float g_rk[16u * 1024u * 1024u];
__device__ float g_rv[16u * 1024u * 1024u];
__device__ float g_rw[4u * 1024u * 1024u];   // Wq|Wk|Wv|Wo rounded
__device__ float g_q [16u * 1024u * 1024u];
__device__ float g_k [16u * 1024u * 1024u];
__device__ float g_v [16u * 1024u * 1024u];
__device__ float g_w [16u * 1024u * 1024u];
__device__ float g_o [16u * 1024u * 1024u];

__device__ __forceinline__ float f2tf(float x) {
    unsigned u;
    asm("cvt.rna.tf32.f32 %0, %1;" : "=r"(u) : "f"(x));
    return __uint_as_float(u);
}
__device__ __forceinline__ void cpa16(uint32_t s, const float* g) {
    asm volatile("cp.async.cg.shared.global [%0], [%1], 16;"
                 :: "r"(s), "l"(g));
}
#define CP_COMMIT() asm volatile("cp.async.commit_group;")
#define CP_WAIT2()  asm volatile("cp.async.wait_group 2;")

__device__ __forceinline__ void mma8(float* d, const float* a, const float* b) {
    asm volatile(
        "mma.sync.aligned.m16n8k8.row.col.f32.tf32.tf32.f32 "
        "{%0,%1,%2,%3}, {%4,%5,%6,%7}, {%8,%9}, {%0,%1,%2,%3};"
        : "+f"(d[0]), "+f"(d[1]), "+f"(d[2]), "+f"(d[3])
        : "r"(__float_as_uint(a[0])), "r"(__float_as_uint(a[1])),
          "r"(__float_as_uint(a[2])), "r"(__float_as_uint(a[3])),
          "r"(__float_as_uint(b[0])), "r"(__float_as_uint(b[1])));
}

// ============================================================================
// Batched GEMM: C[z][m][n] = scale * sum_k A(m,k)*B(n,k) (+ bias[n])
//   AK1:  A(m,k) = A[m*sA + k]   else A(m,k) = A[k*sA + m]   (same for B)
// M,N multiples of 128, K = 1024. C row-major ldC.
// ============================================================================
template <bool AK1, bool BK1, bool BIAS, bool ROUND>
__global__ void __launch_bounds__(128, 2)
gemm_v4(const float* __restrict__ A, const float* __restrict__ B,
        const float* __restrict__ bias, float* __restrict__ C,
        long long bsA, long long bsB, long long bsC,
        int sA, int sB, int ldC, float scale) {
    extern __shared__ float sm[];
    const uint32_t smb = (uint32_t)__cvta_generic_to_shared(sm);

    const int tid  = threadIdx.x;           // 0..127
    const int lane = tid & 31;
    const int warp = tid >> 5;               // 0..3
    const int wm = (warp & 1) << 6;          // 0 / 64
    const int wn = (warp >> 1) << 6;         // 0 / 64
    const int gr = lane >> 2;
    const int kr = lane & 3;
    const int bn = blockIdx.x << 7;
    const int bm = blockIdx.y << 7;

    A += (long long)blockIdx.z * bsA;
    B += (long long)blockIdx.z * bsB;
    C += (long long)blockIdx.z * bsC;

    // ---- cp.async source pointers + smem byte offsets (4 chunks each) ----
    const float* gA[4];
    const float* gB[4];
    uint32_t dA[4], dB[4];
    long long stepA, stepB;
    if (AK1) {
#pragma unroll
        for (int i = 0; i < 4; i++) {
            const int c = tid + (i << 7);
            const int m = c >> 2, kq = c & 3;
            gA[i] = A + (long long)(bm + m) * sA + 4 * kq;
            dA[i] = (uint32_t)(m * LD1 + 4 * kq) * 4u;
        }
        stepA = 16;
    } else {
#pragma unroll
        for (int i = 0; i < 4; i++) {
            const int c = tid + (i << 7);
            const int k = c >> 5, m4 = (c & 31) << 2;
            gA[i] = A + (long long)k * sA + bm + m4;
            dA[i] = (uint32_t)(k * LD2 + m4) * 4u;
        }
        stepA = 16LL * sA;
    }
    if (BK1) {
#pragma unroll
        for (int i = 0; i < 4; i++) {
            const int c = tid + (i << 7);
            const int n = c >> 2, kq = c & 3;
            gB[i] = B + (long long)(bn + n) * sB + 4 * kq;
            dB[i] = (uint32_t)(B_OFF + n * LD1 + 4 * kq) * 4u;
        }
        stepB = 16;
    } else {
#pragma unroll
        for (int i = 0; i < 4; i++) {
            const int c = tid + (i << 7);
            const int k = c >> 5, n4 = (c & 31) << 2;
            gB[i] = B + (long long)k * sB + bn + n4;
            dB[i] = (uint32_t)(B_OFF + k * LD2 + n4) * 4u;
        }
        stepB = 16LL * sB;
    }

    float acc[4][8][4];
#pragma unroll
    for (int i = 0; i < 4; i++)
#pragma unroll
        for (int j = 0; j < 8; j++)
#pragma unroll
            for (int l = 0; l < 4; l++) acc[i][j][l] = 0.f;

    // ---- prologue: stages 0..2 ----
#pragma unroll
    for (int s = 0; s < 3; s++) {
        const uint32_t sb = smb + s * STG_BYTES;
#pragma unroll
        for (int i = 0; i < 4; i++) {
            cpa16(sb + dA[i], gA[i]);
            cpa16(sb + dB[i], gB[i]);
            gA[i] += stepA; gB[i] += stepB;
        }
        CP_COMMIT();
    }

    // ---- main loop over 64 k-tiles ----
    for (int kt = 0; kt < 64; kt++) {
        CP_WAIT2();
        __syncthreads();

        if (kt + 3 < 64) {
            const uint32_t sb = smb + ((kt + 3) & 3) * STG_BYTES;
#pragma unroll
            for (int i = 0; i < 4; i++) {
                cpa16(sb + dA[i], gA[i]);
                cpa16(sb + dB[i], gB[i]);
                gA[i] += stepA; gB[i] += stepB;
            }
        }
        CP_COMMIT();

        const float* As = sm + (kt & 3) * STG_FLOATS;
        const float* Bs = As + B_OFF;
#pragma unroll
        for (int k8 = 0; k8 < 2; k8++) {
            float a[4][4], b[8][2];
            if (AK1) {
#pragma unroll
                for (int mt = 0; mt < 4; mt++) {
                    const float* p = As + (wm + mt * 16 + gr) * LD1 + k8 * 8 + kr;
                    a[mt][0] = p[0];
                    a[mt][1] = p[8 * LD1];
                    a[mt][2] = p[4];
                    a[mt][3] = p[8 * LD1 + 4];
                }
            } else {
#pragma unroll
                for (int mt = 0; mt < 4; mt++) {
                    const float* p = As + (k8 * 8 + kr) * LD2 + wm + mt * 16 + gr;
                    a[mt][0] = p[0];
                    a[mt][1] = p[8];
                    a[mt][2] = p[4 * LD2];
                    a[mt][3] = p[4 * LD2 + 8];
                }
            }
            if (BK1) {
#pragma unroll
                for (int nt = 0; nt < 8; nt++) {
                    const float* p = Bs + (wn + nt * 8 + gr) * LD1 + k8 * 8 + kr;
                    b[nt][0] = p[0];
                    b[nt][1] = p[4];
                }
            } else {
#pragma unroll
                for (int nt = 0; nt < 8; nt++) {
                    const float* p = Bs + (k8 * 8 + kr) * LD2 + wn + nt * 8 + gr;
                    b[nt][0] = p[0];
                    b[nt][1] = p[4 * LD2];
                }
            }
#pragma unroll
            for (int mt = 0; mt < 4; mt++)
#pragma unroll
                for (int nt = 0; nt < 8; nt++)
                    mma8(acc[mt][nt], a[mt], b[nt]);
        }
    }

    // ---- epilogue ----
#pragma unroll
    for (int mt = 0; mt < 4; mt++) {
        const long long r0 = (long long)(bm + wm + mt * 16 + gr) * ldC;
#pragma unroll
        for (int nt = 0; nt < 8; nt++) {
            const int col = bn + wn + nt * 8 + kr * 2;
            float b0 = 0.f, b1 = 0.f;
            if (BIAS) {
                float2 bb = *(const float2*)(bias + col);
                b0 = bb.x; b1 = bb.y;
            }
            float x0 = acc[mt][nt][0] * scale + b0;
            float x1 = acc[mt][nt][1] * scale + b1;
            float x2 = acc[mt][nt][2] * scale + b0;
            float x3 = acc[mt][nt][3] * scale + b1;
            if (ROUND) {
                x0 = f2tf(x0); x1 = f2tf(x1); x2 = f2tf(x2); x3 = f2tf(x3);
            }
            *(float2*)&C[r0 + col] = make_float2(x0, x1);
            *(float2*)&C[r0 + 8LL * ldC + col] = make_float2(x2, x3);
        }
    }
}

// ---------------- pre-round (RNA -> tf32) ------------------------------------
__global__ void round_pass(const float* __restrict__ in, float* __restrict__ out,
                           int n) {
    int i = (blockIdx.x * blockDim.x + threadIdx.x) * 4;
    if (i < n) {
        float4 v = *(const float4*)(in + i);
        v.x = f2tf(v.x); v.y = f2tf(v.y); v.z = f2tf(v.z); v.w = f2tf(v.w);
        *(float4*)(out + i) = v;
    }
}

// ---------------- softmax over rows of 1024, in place, rounds output ---------
__device__ __forceinline__ float warpMax(float v) {
#pragma unroll
    for (int o = 16; o; o >>= 1) v = fmaxf(v, __shfl_xor_sync(0xffffffffu, v, o));
    return v;
}
__device__ __forceinline__ float warpSum(float v) {
#pragma unroll
    for (int o = 16; o; o >>= 1) v += __shfl_xor_sync(0xffffffffu, v, o);
    return v;
}
__global__ void softmax1024(float* __restrict__ W) {
    const long long row = blockIdx.x;
    float4* p = (float4*)(W + row * 1024);
    const int tid = threadIdx.x;  // 256
    float4 x = p[tid];
    float m = fmaxf(fmaxf(x.x, x.y), fmaxf(x.z, x.w));
    m = warpMax(m);
    __shared__ float sm[8], ss[8];
    if ((tid & 31) == 0) sm[tid >> 5] = m;
    __syncthreads();
    if (tid < 32) {
        float v = (tid < 8) ? sm[tid] : -1e30f;
        v = warpMax(v);
        if (tid == 0) sm[0] = v;
    }
    __syncthreads();
    m = sm[0];
    float e0 = __expf(x.x - m), e1 = __expf(x.y - m),
          e2 = __expf(x.z - m), e3 = __expf(x.w - m);
    float s = e0 + e1 + e2 + e3;
    s = warpSum(s);
    if ((tid & 31) == 0) ss[tid >> 5] = s;
    __syncthreads();
    if (tid < 32) {
        float v = (tid < 8) ? ss[tid] : 0.f;
        v = warpSum(v);
        if (tid == 0) ss[0] = v;
    }
    __syncthreads();
    const float inv = 1.0f / ss[0];
    p[tid] = make_float4(f2tf(e0 * inv), f2tf(e1 * inv),
                         f2tf(e2 * inv), f2tf(e3 * inv));
}

// ---------------- host side ---------------------------------------------------
extern "C" void kernel_launch(void* const* d_in, const int* in_sizes, int n_in,
                              void* d_out, int out_size) {
    const float* query = (const float*)d_in[0];
    const float* key   = (const float*)d_in[1];
    const float* value = (const float*)d_in[2];
    const float* Wq = (const float*)d_in[3];
    const float* bq = (const float*)d_in[4];
    const float* Wk = (const float*)d_in[5];
    const float* bk = (const float*)d_in[6];
    const float* Wv = (const float*)d_in[7];
    const float* bv = (const float*)d_in[8];
    const float* Wo = (const float*)d_in[9];
    const float* bo = (const float*)d_in[10];
    float* out = (float*)d_out;

    float *rq, *rk, *rv, *rw, *q, *k, *v, *w, *o;
    cudaGetSymbolAddress((void**)&rq, g_rq);
    cudaGetSymbolAddress((void**)&rk, g_rk);
    cudaGetSymbolAddress((void**)&rv, g_rv);
    cudaGetSymbolAddress((void**)&rw, g_rw);
    cudaGetSymbolAddress((void**)&q, g_q);
    cudaGetSymbolAddress((void**)&k, g_k);
    cudaGetSymbolAddress((void**)&v, g_v);
    cudaGetSymbolAddress((void**)&w, g_w);
    cudaGetSymbolAddress((void**)&o, g_o);

    cudaFuncSetAttribute(gemm_v4<true, true, true, true>,
                         cudaFuncAttributeMaxDynamicSharedMemorySize, SMEM_BYTES);
    cudaFuncSetAttribute(gemm_v4<false, true, false, false>,
                         cudaFuncAttributeMaxDynamicSharedMemorySize, SMEM_BYTES);
    cudaFuncSetAttribute(gemm_v4<true, false, false, true>,
                         cudaFuncAttributeMaxDynamicSharedMemorySize, SMEM_BYTES);
    cudaFuncSetAttribute(gemm_v4<true, true, true, false>,
                         cudaFuncAttributeMaxDynamicSharedMemorySize, SMEM_BYTES);

    const int BIG = 16 * 1024 * 1024, WSZ = 1024 * 1024;
    round_pass<<<BIG / 1024, 256>>>(query, rq, BIG);
    round_pass<<<BIG / 1024, 256>>>(key, rk, BIG);
    round_pass<<<BIG / 1024, 256>>>(value, rv, BIG);
    round_pass<<<WSZ / 1024, 256>>>(Wq, rw + 0 * WSZ, WSZ);
    round_pass<<<WSZ / 1024, 256>>>(Wk, rw + 1 * WSZ, WSZ);
    round_pass<<<WSZ / 1024, 256>>>(Wv, rw + 2 * WSZ, WSZ);
    round_pass<<<WSZ / 1024, 256>>>(Wo, rw + 3 * WSZ, WSZ);

    const long long MB = 1024LL * 1024LL;
    dim3 blk(128);
    dim3 gp(8, 128, 1);   // projections: N=1024, M=16384
    dim3 ga(8, 8, 16);    // attention:   N=1024, M=1024, batch 16

    // q/k/v = X @ W^T + b (k-unit both), rounded outputs
    gemm_v4<true, true, true, true><<<gp, blk, SMEM_BYTES>>>(
        rq, rw + 0 * WSZ, bq, q, 0, 0, 0, 1024, 1024, 1024, 1.0f);
    gemm_v4<true, true, true, true><<<gp, blk, SMEM_BYTES>>>(
        rk, rw + 1 * WSZ, bk, k, 0, 0, 0, 1024, 1024, 1024, 1.0f);
    gemm_v4<true, true, true, true><<<gp, blk, SMEM_BYTES>>>(
        rv, rw + 2 * WSZ, bv, v, 0, 0, 0, 1024, 1024, 1024, 1.0f);

    // w[b,i,s] = (1/32) sum_t q[b,t,i]*k[b,s,t]: A=q m-unit, B=k k-unit
    gemm_v4<false, true, false, false><<<ga, blk, SMEM_BYTES>>>(
        q, k, nullptr, w, MB, MB, MB, 1024, 1024, 1024, 0.03125f);

    softmax1024<<<16 * 1024, 256>>>(w);

    // o[b,i,e] = sum_s a[b,i,s]*v[b,s,e]: A=w k-unit, B=v n-unit
    gemm_v4<true, false, false, true><<<ga, blk, SMEM_BYTES>>>(
        w, v, nullptr, o, MB, MB, MB, 1024, 1024, 1024, 1.0f);

    // out = o @ Wo^T + bo
    gemm_v4<true, true, true, false><<<gp, blk, SMEM_BYTES>>>(
        o, rw + 3 * WSZ, bo, out, 0, 0, 0, 1024, 1024, 1024, 1.0f);
}